// round 8
// baseline (speedup 1.0000x reference)
#include <cuda_runtime.h>
#include <cstdint>

#define NUM_NEURONS 8192
#define INPUT_SIZE  8192
#define BATCH       2048

#define THREADS 1024
#define NPT     8                  // neurons per thread (2 groups of 4)
#define NGROUP  (NPT / 4)          // 2
#define GRID    148                // persistent: 1 block per SM
#define PAIRS   (BATCH / 2)        // 1024 row-pairs
#define PAIR_BYTES (2 * INPUT_SIZE * 4)   // 64 KB
#define NBUF    2

// Per-neuron collapsed coefficients: out = A + B*a1 + C*a2 + D*a1*a2
__device__ float4 g_coeff[NUM_NEURONS];

// ---------------------------------------------------------------------------
// PTX helpers (mbarrier + 1D TMA bulk copy)
// ---------------------------------------------------------------------------
__device__ __forceinline__ uint32_t smem_u32(const void* p) {
    uint32_t a;
    asm("{ .reg .u64 t; cvta.to.shared.u64 t, %1; cvt.u32.u64 %0, t; }"
        : "=r"(a) : "l"(p));
    return a;
}
__device__ __forceinline__ void mbar_init(uint32_t m, uint32_t cnt) {
    asm volatile("mbarrier.init.shared.b64 [%0], %1;" :: "r"(m), "r"(cnt) : "memory");
}
__device__ __forceinline__ void mbar_expect_tx(uint32_t m, uint32_t bytes) {
    asm volatile("mbarrier.arrive.expect_tx.shared.b64 _, [%0], %1;"
                 :: "r"(m), "r"(bytes) : "memory");
}
__device__ __forceinline__ void mbar_wait(uint32_t m, uint32_t phase) {
    asm volatile(
        "{\n\t.reg .pred P;\n\t"
        "WL_%=:\n\t"
        "mbarrier.try_wait.parity.acquire.cta.shared::cta.b64 P, [%0], %1, 0x989680;\n\t"
        "@P bra WD_%=;\n\t"
        "bra WL_%=;\n\t"
        "WD_%=:\n\t}"
        :: "r"(m), "r"(phase) : "memory");
}
__device__ __forceinline__ void tma_bulk_g2s(uint32_t dst_smem, const void* src,
                                             uint32_t bytes, uint32_t mbar) {
    asm volatile(
        "cp.async.bulk.shared::cluster.global.mbarrier::complete_tx::bytes "
        "[%0], [%1], %2, [%3];"
        :: "r"(dst_smem), "l"(src), "r"(bytes), "r"(mbar) : "memory");
}

// ---------------------------------------------------------------------------
// Precompute: softmax(w[n,:16]) dotted with the constant coefficient vectors
// of the 16 affine-in-(1,a1,a2,a1*a2) logic ops.
// ---------------------------------------------------------------------------
__global__ void coeff_kernel(const float* __restrict__ w) {
    int n = blockIdx.x * blockDim.x + threadIdx.x;
    if (n >= NUM_NEURONS) return;

    const float4* wr = reinterpret_cast<const float4*>(w) + n * 4;
    float v[16];
    float4 t;
    t = wr[0]; v[0]=t.x;  v[1]=t.y;  v[2]=t.z;  v[3]=t.w;
    t = wr[1]; v[4]=t.x;  v[5]=t.y;  v[6]=t.z;  v[7]=t.w;
    t = wr[2]; v[8]=t.x;  v[9]=t.y;  v[10]=t.z; v[11]=t.w;
    t = wr[3]; v[12]=t.x; v[13]=t.y; v[14]=t.z; v[15]=t.w;

    float m = v[0];
#pragma unroll
    for (int i = 1; i < 16; i++) m = fmaxf(m, v[i]);
    float s = 0.0f;
#pragma unroll
    for (int i = 0; i < 16; i++) { v[i] = __expf(v[i] - m); s += v[i]; }
    float inv = 1.0f / s;
#pragma unroll
    for (int i = 0; i < 16; i++) v[i] *= inv;

    //  0:0  1:p  2:a1-p  3:a1  4:a2-p  5:a2  6:a1+a2-2p  7:a1+a2-p
    //  8:1-(a1+a2-p)  9:1-(a1+a2-2p)  10:1-a2  11:1-a2+p
    // 12:1-a1  13:1-a1+p  14:1-p  15:1
    float A = v[8]+v[9]+v[10]+v[11]+v[12]+v[13]+v[14]+v[15];
    float B = (v[2]+v[3]+v[6]+v[7]) - (v[8]+v[9]+v[12]+v[13]);
    float C = (v[4]+v[5]+v[6]+v[7]) - (v[8]+v[9]+v[10]+v[11]);
    float D = v[1]-v[2]-v[4]-2.0f*v[6]-v[7]+v[8]+2.0f*v[9]+v[11]+v[13]-v[14];

    g_coeff[n] = make_float4(A, B, C, D);
}

// ---------------------------------------------------------------------------
// Persistent main kernel (R5 schedule, doubled warps). grid=148, 1 block/SM,
// 1024 threads (32 warps), 2 x 64KB TMA ring buffers. Prefetch for pair k+2
// is issued right after the end-of-pair __syncthreads (the schedule that
// measured fastest). idx+coeff register-resident: 8 neurons/thread keeps the
// block under 64 regs/thread so the full 64K RF holds 1024 threads.
// ---------------------------------------------------------------------------
__global__ __launch_bounds__(THREADS, 1) void logic_kernel(
    const float* __restrict__ x,
    const int*   __restrict__ idx,
    float* __restrict__ out)
{
    extern __shared__ __align__(128) char smem[];
    float* buf0 = reinterpret_cast<float*>(smem);                 // 64 KB
    float* buf1 = reinterpret_cast<float*>(smem + PAIR_BYTES);    // 64 KB
    const uint32_t mbar0 = smem_u32(smem + 2 * PAIR_BYTES);
    const uint32_t mbar1 = mbar0 + 8;

    const int tid = threadIdx.x;
    const int bid = blockIdx.x;

    // --- Preload idx (packed u16 pairs) + coefficients into registers ---
    uint32_t pidx[NPT];
    float4   cf[NPT];
    const int4* idx4 = reinterpret_cast<const int4*>(idx);  // 2 neurons per int4
#pragma unroll
    for (int g = 0; g < NGROUP; g++) {
        int nbase = g * (4 * THREADS) + tid * 4;   // 4 consecutive neurons
        int4 ia = __ldg(&idx4[nbase / 2]);         // neurons nbase, nbase+1
        int4 ib = __ldg(&idx4[nbase / 2 + 1]);     // neurons nbase+2, nbase+3
        pidx[g * 4 + 0] = (uint32_t)ia.x | ((uint32_t)ia.y << 16);
        pidx[g * 4 + 1] = (uint32_t)ia.z | ((uint32_t)ia.w << 16);
        pidx[g * 4 + 2] = (uint32_t)ib.x | ((uint32_t)ib.y << 16);
        pidx[g * 4 + 3] = (uint32_t)ib.z | ((uint32_t)ib.w << 16);
#pragma unroll
        for (int u = 0; u < 4; u++) cf[g * 4 + u] = g_coeff[nbase + u];
    }

    if (tid == 0) { mbar_init(mbar0, 1); mbar_init(mbar1, 1); }
    __syncthreads();

    const int npairs = (PAIRS - bid + GRID - 1) / GRID;   // 6 or 7

    // --- Prologue: issue first two TMA loads ---
    if (tid == 0) {
        if (npairs > 0) {
            mbar_expect_tx(mbar0, PAIR_BYTES);
            tma_bulk_g2s(smem_u32(buf0), x + (size_t)bid * 2 * INPUT_SIZE,
                         PAIR_BYTES, mbar0);
        }
        if (npairs > 1) {
            mbar_expect_tx(mbar1, PAIR_BYTES);
            tma_bulk_g2s(smem_u32(buf1), x + (size_t)(bid + GRID) * 2 * INPUT_SIZE,
                         PAIR_BYTES, mbar1);
        }
    }

    uint32_t phases = 0;   // bit b = current wait parity of buffer b

    for (int k = 0; k < npairs; k++) {
        const int b = k & 1;
        const float* xs0 = b ? buf1 : buf0;
        const float* xs1 = xs0 + INPUT_SIZE;
        const uint32_t mb = b ? mbar1 : mbar0;

        mbar_wait(mb, (phases >> b) & 1u);
        phases ^= (1u << b);

        const int p = bid + k * GRID;
        float4* o0 = reinterpret_cast<float4*>(out + (size_t)(2 * p)     * NUM_NEURONS);
        float4* o1 = reinterpret_cast<float4*>(out + (size_t)(2 * p + 1) * NUM_NEURONS);

#pragma unroll
        for (int g = 0; g < NGROUP; g++) {
            float4 r0, r1;
            float* q0 = reinterpret_cast<float*>(&r0);
            float* q1 = reinterpret_cast<float*>(&r1);
#pragma unroll
            for (int u = 0; u < 4; u++) {
                const uint32_t pk = pidx[g * 4 + u];
                const int i1 = pk & 0xFFFFu;
                const int i2 = pk >> 16;
                const float a10 = xs0[i1], a20 = xs0[i2];
                const float a11 = xs1[i1], a21 = xs1[i2];
                const float4 c = cf[g * 4 + u];
                q0[u] = fmaf(a10, fmaf(a20, c.w, c.y), fmaf(a20, c.z, c.x));
                q1[u] = fmaf(a11, fmaf(a21, c.w, c.y), fmaf(a21, c.z, c.x));
            }
            const int o = g * THREADS + tid;   // coalesced float4 stores
            o0[o] = r0;
            o1[o] = r1;
        }

        __syncthreads();   // everyone done reading buffer b

        if (tid == 0 && k + 2 < npairs) {
            mbar_expect_tx(mb, PAIR_BYTES);
            tma_bulk_g2s(smem_u32(b ? buf1 : buf0),
                         x + (size_t)(bid + (k + 2) * GRID) * 2 * INPUT_SIZE,
                         PAIR_BYTES, mb);
        }
    }
}

extern "C" void kernel_launch(void* const* d_in, const int* in_sizes, int n_in,
                              void* d_out, int out_size) {
    const float* x    = (const float*)d_in[0];   // [2048, 8192] f32
    const float* w    = (const float*)d_in[1];   // [8192, 16]   f32
    const int*   conn = (const int*)d_in[2];     // [8192, 2]    i32
    float* out = (float*)d_out;                  // [2048, 8192] f32

    const int smem = NBUF * PAIR_BYTES + 16;     // 128 KB buffers + 2 mbarriers
    cudaFuncSetAttribute(logic_kernel,
                         cudaFuncAttributeMaxDynamicSharedMemorySize, smem);

    coeff_kernel<<<NUM_NEURONS / 256, 256>>>(w);
    logic_kernel<<<GRID, THREADS, smem>>>(x, conn, out);
}

// round 9
// speedup vs baseline: 1.0691x; 1.0691x over previous
#include <cuda_runtime.h>
#include <cuda_fp16.h>
#include <cstdint>

#define NUM_NEURONS 8192
#define INPUT_SIZE  8192
#define BATCH       2048

#define THREADS 1024
#define NPT     8                  // neurons per thread (2 groups of 4)
#define NGROUP  (NPT / 4)          // 2
#define GRID    148                // persistent: 1 block per SM
#define PAIRS   (BATCH / 2)        // 1024 row-pairs
#define PAIR_BYTES (2 * INPUT_SIZE * 4)   // 64 KB fp32 pair
#define NBUF    2

// Per-neuron collapsed coefficients: out = A + B*a1 + C*a2 + D*a1*a2
__device__ float4 g_coeff[NUM_NEURONS];

// ---------------------------------------------------------------------------
// PTX helpers (mbarrier + 1D TMA bulk copy)
// ---------------------------------------------------------------------------
__device__ __forceinline__ uint32_t smem_u32(const void* p) {
    uint32_t a;
    asm("{ .reg .u64 t; cvta.to.shared.u64 t, %1; cvt.u32.u64 %0, t; }"
        : "=r"(a) : "l"(p));
    return a;
}
__device__ __forceinline__ void mbar_init(uint32_t m, uint32_t cnt) {
    asm volatile("mbarrier.init.shared.b64 [%0], %1;" :: "r"(m), "r"(cnt) : "memory");
}
__device__ __forceinline__ void mbar_expect_tx(uint32_t m, uint32_t bytes) {
    asm volatile("mbarrier.arrive.expect_tx.shared.b64 _, [%0], %1;"
                 :: "r"(m), "r"(bytes) : "memory");
}
__device__ __forceinline__ void mbar_wait(uint32_t m, uint32_t phase) {
    asm volatile(
        "{\n\t.reg .pred P;\n\t"
        "WL_%=:\n\t"
        "mbarrier.try_wait.parity.acquire.cta.shared::cta.b64 P, [%0], %1, 0x989680;\n\t"
        "@P bra WD_%=;\n\t"
        "bra WL_%=;\n\t"
        "WD_%=:\n\t}"
        :: "r"(m), "r"(phase) : "memory");
}
__device__ __forceinline__ void tma_bulk_g2s(uint32_t dst_smem, const void* src,
                                             uint32_t bytes, uint32_t mbar) {
    asm volatile(
        "cp.async.bulk.shared::cluster.global.mbarrier::complete_tx::bytes "
        "[%0], [%1], %2, [%3];"
        :: "r"(dst_smem), "l"(src), "r"(bytes), "r"(mbar) : "memory");
}

// ---------------------------------------------------------------------------
// Precompute: softmax(w[n,:16]) dotted with the constant coefficient vectors
// of the 16 affine-in-(1,a1,a2,a1*a2) logic ops.
// ---------------------------------------------------------------------------
__global__ void coeff_kernel(const float* __restrict__ w) {
    int n = blockIdx.x * blockDim.x + threadIdx.x;
    if (n >= NUM_NEURONS) return;

    const float4* wr = reinterpret_cast<const float4*>(w) + n * 4;
    float v[16];
    float4 t;
    t = wr[0]; v[0]=t.x;  v[1]=t.y;  v[2]=t.z;  v[3]=t.w;
    t = wr[1]; v[4]=t.x;  v[5]=t.y;  v[6]=t.z;  v[7]=t.w;
    t = wr[2]; v[8]=t.x;  v[9]=t.y;  v[10]=t.z; v[11]=t.w;
    t = wr[3]; v[12]=t.x; v[13]=t.y; v[14]=t.z; v[15]=t.w;

    float m = v[0];
#pragma unroll
    for (int i = 1; i < 16; i++) m = fmaxf(m, v[i]);
    float s = 0.0f;
#pragma unroll
    for (int i = 0; i < 16; i++) { v[i] = __expf(v[i] - m); s += v[i]; }
    float inv = 1.0f / s;
#pragma unroll
    for (int i = 0; i < 16; i++) v[i] *= inv;

    //  0:0  1:p  2:a1-p  3:a1  4:a2-p  5:a2  6:a1+a2-2p  7:a1+a2-p
    //  8:1-(a1+a2-p)  9:1-(a1+a2-2p)  10:1-a2  11:1-a2+p
    // 12:1-a1  13:1-a1+p  14:1-p  15:1
    float A = v[8]+v[9]+v[10]+v[11]+v[12]+v[13]+v[14]+v[15];
    float B = (v[2]+v[3]+v[6]+v[7]) - (v[8]+v[9]+v[12]+v[13]);
    float C = (v[4]+v[5]+v[6]+v[7]) - (v[8]+v[9]+v[10]+v[11]);
    float D = v[1]-v[2]-v[4]-2.0f*v[6]-v[7]+v[8]+2.0f*v[9]+v[11]+v[13]-v[14];

    g_coeff[n] = make_float4(A, B, C, D);
}

// ---------------------------------------------------------------------------
// Persistent main kernel. grid=148, 1 block/SM, 1024 threads.
// Per pair: TMA brings the fp32 row pair (64KB); a conflict-free convert pass
// packs it into half2 {row0[i], row1[i]} (32KB). Gathers then fetch BOTH rows
// with a single LDS.32 — halving the dominant conflict-wavefront stream.
// Math stays fp32 (only staged inputs are fp16). The fp32 buffer is free as
// soon as the convert barrier passes, so the TMA for pair k+2 is issued there
// and overlaps the gather/compute of pair k.
// ---------------------------------------------------------------------------
__global__ __launch_bounds__(THREADS, 1) void logic_kernel(
    const float* __restrict__ x,
    const int*   __restrict__ idx,
    float* __restrict__ out)
{
    extern __shared__ __align__(128) char smem[];
    float*   buf0 = reinterpret_cast<float*>(smem);                  // 64 KB fp32
    float*   buf1 = reinterpret_cast<float*>(smem + PAIR_BYTES);     // 64 KB fp32
    __half2* xh   = reinterpret_cast<__half2*>(smem + 2 * PAIR_BYTES); // 32 KB
    const uint32_t mbar0 = smem_u32(smem + 2 * PAIR_BYTES + INPUT_SIZE * 4);
    const uint32_t mbar1 = mbar0 + 8;

    const int tid = threadIdx.x;
    const int bid = blockIdx.x;

    // --- Preload idx (packed u16 pairs) + coefficients into registers ---
    uint32_t pidx[NPT];
    float4   cf[NPT];
    const int4* idx4 = reinterpret_cast<const int4*>(idx);  // 2 neurons per int4
#pragma unroll
    for (int g = 0; g < NGROUP; g++) {
        int nbase = g * (4 * THREADS) + tid * 4;   // 4 consecutive neurons
        int4 ia = __ldg(&idx4[nbase / 2]);         // neurons nbase, nbase+1
        int4 ib = __ldg(&idx4[nbase / 2 + 1]);     // neurons nbase+2, nbase+3
        pidx[g * 4 + 0] = (uint32_t)ia.x | ((uint32_t)ia.y << 16);
        pidx[g * 4 + 1] = (uint32_t)ia.z | ((uint32_t)ia.w << 16);
        pidx[g * 4 + 2] = (uint32_t)ib.x | ((uint32_t)ib.y << 16);
        pidx[g * 4 + 3] = (uint32_t)ib.z | ((uint32_t)ib.w << 16);
#pragma unroll
        for (int u = 0; u < 4; u++) cf[g * 4 + u] = g_coeff[nbase + u];
    }

    if (tid == 0) { mbar_init(mbar0, 1); mbar_init(mbar1, 1); }
    __syncthreads();

    const int npairs = (PAIRS - bid + GRID - 1) / GRID;   // 6 or 7

    // --- Prologue: issue first two TMA loads ---
    if (tid == 0) {
        if (npairs > 0) {
            mbar_expect_tx(mbar0, PAIR_BYTES);
            tma_bulk_g2s(smem_u32(buf0), x + (size_t)bid * 2 * INPUT_SIZE,
                         PAIR_BYTES, mbar0);
        }
        if (npairs > 1) {
            mbar_expect_tx(mbar1, PAIR_BYTES);
            tma_bulk_g2s(smem_u32(buf1), x + (size_t)(bid + GRID) * 2 * INPUT_SIZE,
                         PAIR_BYTES, mbar1);
        }
    }

    uint32_t phases = 0;   // bit b = current wait parity of buffer b

    for (int k = 0; k < npairs; k++) {
        const int b = k & 1;
        const float* bf = b ? buf1 : buf0;
        const uint32_t mb = b ? mbar1 : mbar0;

        mbar_wait(mb, (phases >> b) & 1u);
        phases ^= (1u << b);

        // --- Convert pass: pack {row0[c], row1[c]} -> half2. Conflict-free. ---
#pragma unroll
        for (int c = tid; c < INPUT_SIZE; c += THREADS)
            xh[c] = __floats2half2_rn(bf[c], bf[c + INPUT_SIZE]);
        __syncthreads();   // xh ready; fp32 buffer b is now dead

        // fp32 buffer b free -> prefetch pair k+2 immediately (overlaps gather)
        if (tid == 0 && k + 2 < npairs) {
            mbar_expect_tx(mb, PAIR_BYTES);
            tma_bulk_g2s(smem_u32(b ? buf1 : buf0),
                         x + (size_t)(bid + (k + 2) * GRID) * 2 * INPUT_SIZE,
                         PAIR_BYTES, mb);
        }

        const int p = bid + k * GRID;
        float4* o0 = reinterpret_cast<float4*>(out + (size_t)(2 * p)     * NUM_NEURONS);
        float4* o1 = reinterpret_cast<float4*>(out + (size_t)(2 * p + 1) * NUM_NEURONS);

#pragma unroll
        for (int g = 0; g < NGROUP; g++) {
            float4 r0, r1;
            float* q0 = reinterpret_cast<float*>(&r0);
            float* q1 = reinterpret_cast<float*>(&r1);
#pragma unroll
            for (int u = 0; u < 4; u++) {
                const uint32_t pk = pidx[g * 4 + u];
                const int i1 = pk & 0xFFFFu;
                const int i2 = pk >> 16;
                const float2 a = __half22float2(xh[i1]);   // {row0, row1} @ i1
                const float2 c2 = __half22float2(xh[i2]);  // {row0, row1} @ i2
                const float4 c = cf[g * 4 + u];
                q0[u] = fmaf(a.x, fmaf(c2.x, c.w, c.y), fmaf(c2.x, c.z, c.x));
                q1[u] = fmaf(a.y, fmaf(c2.y, c.w, c.y), fmaf(c2.y, c.z, c.x));
            }
            const int o = g * THREADS + tid;   // coalesced float4 stores
            o0[o] = r0;
            o1[o] = r1;
        }

        __syncthreads();   // all reads of xh done before next pair's convert
    }
}

extern "C" void kernel_launch(void* const* d_in, const int* in_sizes, int n_in,
                              void* d_out, int out_size) {
    const float* x    = (const float*)d_in[0];   // [2048, 8192] f32
    const float* w    = (const float*)d_in[1];   // [8192, 16]   f32
    const int*   conn = (const int*)d_in[2];     // [8192, 2]    i32
    float* out = (float*)d_out;                  // [2048, 8192] f32

    const int smem = NBUF * PAIR_BYTES + INPUT_SIZE * 4 + 16;  // 160 KB + mbars
    cudaFuncSetAttribute(logic_kernel,
                         cudaFuncAttributeMaxDynamicSharedMemorySize, smem);

    coeff_kernel<<<NUM_NEURONS / 256, 256>>>(w);
    logic_kernel<<<GRID, THREADS, smem>>>(x, conn, out);
}